// round 1
// baseline (speedup 1.0000x reference)
#include <cuda_runtime.h>
#include <math.h>

#define BB 64
#define TT 4096
#define DD 128
#define HH 128
#define GG 384   // 3*H, gates packed [r, z, n]

// Scratch (device globals — no allocation allowed in kernel_launch).
__device__ float g_gi[(size_t)TT * BB * GG];   // input-projection gates, layout [t][b][3H]
__device__ float g_h0[(size_t)TT * BB * HH];   // layer-0 hidden states,   layout [t][b][H]

// ---------------------------------------------------------------------------
// GEMM: g_gi[m][j] = dot(in_row(m), W[j]) + bias[j],  m = t*B + b in [0, T*B)
//   mode 0: input row = X + (b*T + t)*D   (x is [B,T,D])
//   mode 1: input row = g_h0 + m*H        (h0 is [T,B,H])
// Weights-in-registers: thread j holds W row j (128 regs); rows of the
// activation matrix are broadcast from shared. FFMA-pipe bound: 64 MAC/cyc/SM.
// ---------------------------------------------------------------------------
__global__ __launch_bounds__(384, 1) void gi_gemm(
    const float* __restrict__ X,
    const float* __restrict__ W,
    const float* __restrict__ bias,
    int mode)
{
    const int j = threadIdx.x;

    float w[128];
    {
        const float4* wr = (const float4*)(W + (size_t)j * 128);
        #pragma unroll
        for (int k = 0; k < 32; k++) {
            float4 v = wr[k];
            w[4*k+0] = v.x; w[4*k+1] = v.y; w[4*k+2] = v.z; w[4*k+3] = v.w;
        }
    }
    const float bj = bias[j];

    __shared__ float sx[4][128];

    const int total = TT * BB;
    const int chunk = (total + gridDim.x - 1) / gridDim.x;
    const int m0 = blockIdx.x * chunk;
    const int m1 = (m0 + chunk < total) ? (m0 + chunk) : total;

    for (int m = m0; m < m1; m += 4) {
        const int nr = (m1 - m < 4) ? (m1 - m) : 4;
        // Cooperative load of up to 4 activation rows into shared.
        for (int i = j; i < nr * 128; i += 384) {
            const int r = i >> 7;
            const int c = i & 127;
            const int mm = m + r;
            const float* src;
            if (mode == 0) {
                const int t = mm >> 6;      // m / B
                const int b = mm & 63;      // m % B
                src = X + ((size_t)b * TT + t) * DD;
            } else {
                src = g_h0 + (size_t)mm * HH;
            }
            sx[r][c] = src[c];
        }
        __syncthreads();

        float a0 = bj, a1 = bj, a2 = bj, a3 = bj;
        const float4* r0 = (const float4*)sx[0];
        const float4* r1 = (const float4*)sx[1];
        const float4* r2 = (const float4*)sx[2];
        const float4* r3 = (const float4*)sx[3];
        #pragma unroll
        for (int k = 0; k < 32; k++) {
            float4 v0 = r0[k], v1 = r1[k], v2 = r2[k], v3 = r3[k];
            a0 = fmaf(v0.x, w[4*k+0], a0); a0 = fmaf(v0.y, w[4*k+1], a0);
            a0 = fmaf(v0.z, w[4*k+2], a0); a0 = fmaf(v0.w, w[4*k+3], a0);
            a1 = fmaf(v1.x, w[4*k+0], a1); a1 = fmaf(v1.y, w[4*k+1], a1);
            a1 = fmaf(v1.z, w[4*k+2], a1); a1 = fmaf(v1.w, w[4*k+3], a1);
            a2 = fmaf(v2.x, w[4*k+0], a2); a2 = fmaf(v2.y, w[4*k+1], a2);
            a2 = fmaf(v2.z, w[4*k+2], a2); a2 = fmaf(v2.w, w[4*k+3], a2);
            a3 = fmaf(v3.x, w[4*k+0], a3); a3 = fmaf(v3.y, w[4*k+1], a3);
            a3 = fmaf(v3.z, w[4*k+2], a3); a3 = fmaf(v3.w, w[4*k+3], a3);
        }
        if (nr > 0) g_gi[(size_t)(m + 0) * GG + j] = a0;
        if (nr > 1) g_gi[(size_t)(m + 1) * GG + j] = a1;
        if (nr > 2) g_gi[(size_t)(m + 2) * GG + j] = a2;
        if (nr > 3) g_gi[(size_t)(m + 3) * GG + j] = a3;
        __syncthreads();
    }
}

// ---------------------------------------------------------------------------
// Sequential GRU recurrence for one layer. One CTA per batch element
// (64 CTAs, independent — no cross-SM sync). Thread j owns gate row j of
// W_hh in registers; h is broadcast from shared memory each step.
//   gh_j = b_hh[j] + dot(h, W_hh[j])
//   r = sig(gi_r + gh_r); z = sig(gi_z + gh_z); n = tanh(gi_n + r*gh_n)
//   h' = (1-z)*n + z*h
// ---------------------------------------------------------------------------
__global__ __launch_bounds__(384, 1) void gru_rec(
    const float* __restrict__ Whh,
    const float* __restrict__ bhh,
    int store_h0,                // 1: write h to g_h0 every step (layer 0)
    float* __restrict__ hout)    // final hidden, 128 floats at hout[b*H + i]
{
    const int j = threadIdx.x;
    const int b = blockIdx.x;

    float w[128];
    {
        const float4* wr = (const float4*)(Whh + (size_t)j * 128);
        #pragma unroll
        for (int k = 0; k < 32; k++) {
            float4 v = wr[k];
            w[4*k+0] = v.x; w[4*k+1] = v.y; w[4*k+2] = v.z; w[4*k+3] = v.w;
        }
    }
    const float bj = bhh[j];

    __shared__ float s_h[128];
    __shared__ float s_gh[384];
    __shared__ float s_gin[128];

    if (j < 128) s_h[j] = 0.0f;
    __syncthreads();

    const float* gptr = g_gi + (size_t)b * GG + j;   // stride B*G per step
    float gval = gptr[0];

    for (int t = 0; t < TT; t++) {
        // Prefetch next step's gi (hidden behind the 128-FFMA dot below).
        float gnext = (t + 1 < TT) ? gptr[(size_t)(t + 1) * BB * GG] : 0.0f;

        float acc = bj;
        const float4* h4 = (const float4*)s_h;
        #pragma unroll
        for (int k = 0; k < 32; k++) {
            float4 hv = h4[k];   // broadcast LDS.128 (conflict-free)
            acc = fmaf(hv.x, w[4*k+0], acc);
            acc = fmaf(hv.y, w[4*k+1], acc);
            acc = fmaf(hv.z, w[4*k+2], acc);
            acc = fmaf(hv.w, w[4*k+3], acc);
        }

        if (j < 256) {
            s_gh[j] = acc + gval;          // r and z rows: gi + gh fused
        } else {
            s_gh[j] = acc;                 // n row: keep gh separate (r scales it)
            s_gin[j - 256] = gval;
        }
        __syncthreads();

        if (j < 128) {
            const float gr  = s_gh[j];
            const float gz  = s_gh[j + 128];
            const float ghn = s_gh[j + 256];
            const float gin = s_gin[j];
            const float r = 1.0f / (1.0f + __expf(-gr));
            const float z = 1.0f / (1.0f + __expf(-gz));
            const float n = tanhf(gin + r * ghn);
            const float hn = (1.0f - z) * n + z * s_h[j];
            s_h[j] = hn;
            if (store_h0)
                g_h0[(size_t)t * BB * HH + (size_t)b * HH + j] = hn;
        }
        __syncthreads();
        gval = gnext;
    }

    if (j < 128) hout[(size_t)b * HH + j] = s_h[j];
}

// ---------------------------------------------------------------------------
// Launch: GEMM0 -> rec0 (stores h0 trajectory) -> GEMM1 -> rec1.
// All plain default-stream launches; graph-capturable; no allocations.
// ---------------------------------------------------------------------------
extern "C" void kernel_launch(void* const* d_in, const int* in_sizes, int n_in,
                              void* d_out, int out_size)
{
    const float* x     = (const float*)d_in[0];
    const float* W_ih0 = (const float*)d_in[1];
    const float* W_hh0 = (const float*)d_in[2];
    const float* b_ih0 = (const float*)d_in[3];
    const float* b_hh0 = (const float*)d_in[4];
    const float* W_ih1 = (const float*)d_in[5];
    const float* W_hh1 = (const float*)d_in[6];
    const float* b_ih1 = (const float*)d_in[7];
    const float* b_hh1 = (const float*)d_in[8];
    float* out = (float*)d_out;   // [L=2, B, H]

    gi_gemm<<<148, 384>>>(x, W_ih0, b_ih0, /*mode=*/0);
    gru_rec<<<BB, 384>>>(W_hh0, b_hh0, /*store_h0=*/1, out);
    gi_gemm<<<148, 384>>>(nullptr, W_ih1, b_ih1, /*mode=*/1);
    gru_rec<<<BB, 384>>>(W_hh1, b_hh1, /*store_h0=*/0, out + BB * HH);
}

// round 2
// speedup vs baseline: 1.0673x; 1.0673x over previous
#include <cuda_runtime.h>
#include <math.h>

#define BB 64
#define TT 4096
#define DD 128
#define HH 128
#define GG 384   // 3*H, gates packed [r, z, n]

typedef unsigned long long u64;

// Scratch (device globals — no allocation allowed in kernel_launch).
__device__ float g_gi[(size_t)TT * BB * GG];   // input-projection gates, [t][b][3H]
__device__ float g_h0[(size_t)TT * BB * HH];   // layer-0 hidden states,  [t][b][H]

// ---- packed f32x2 helpers ------------------------------------------------
__device__ __forceinline__ void fma2(u64& d, u64 a, u64 b) {
    asm("fma.rn.f32x2 %0, %1, %2, %0;" : "+l"(d) : "l"(a), "l"(b));
}
__device__ __forceinline__ u64 f2u(float x, float y) {
    u64 v; asm("mov.b64 %0, {%1,%2};" : "=l"(v) : "f"(x), "f"(y)); return v;
}
__device__ __forceinline__ float2 u2f(u64 v) {
    float2 r; asm("mov.b64 {%0,%1}, %2;" : "=f"(r.x), "=f"(r.y) : "l"(v)); return r;
}
__device__ __forceinline__ float hsum(u64 a, u64 b) {
    float2 x = u2f(a), y = u2f(b);
    return (x.x + x.y) + (y.x + y.y);
}
__device__ __forceinline__ float fsig(float x) {
    return __fdividef(1.0f, 1.0f + __expf(-x));
}
__device__ __forceinline__ float ftanh(float x) {
    // tanh(x) = 1 - 2/(exp(2x)+1); exact at both saturations.
    return 1.0f - __fdividef(2.0f, __expf(2.0f * x) + 1.0f);
}

// ---------------------------------------------------------------------------
// GEMM: g_gi[m][j] = dot(in_row(m), W[j]) + bias[j],  m = t*B + b
//   mode 0: input row = X + (b*T + t)*D   (x is [B,T,D])
//   mode 1: input row = g_h0 + m*H        (h0 is [T,B,H])
// Weights-in-registers (64 packed pairs/thread); rows broadcast from shared.
// ---------------------------------------------------------------------------
__global__ __launch_bounds__(384, 1) void gi_gemm(
    const float* __restrict__ X,
    const float* __restrict__ W,
    const float* __restrict__ bias,
    int mode)
{
    const int j = threadIdx.x;

    u64 w[64];
    {
        const ulonglong2* wr = (const ulonglong2*)(W + (size_t)j * 128);
        #pragma unroll
        for (int k = 0; k < 32; k++) { ulonglong2 v = wr[k]; w[2*k] = v.x; w[2*k+1] = v.y; }
    }
    const float bj = bias[j];

    __shared__ __align__(16) float sx[4][128];

    const int total = TT * BB;
    const int chunk = (total + gridDim.x - 1) / gridDim.x;
    const int m0 = blockIdx.x * chunk;
    const int m1 = (m0 + chunk < total) ? (m0 + chunk) : total;

    for (int m = m0; m < m1; m += 4) {
        const int nr = (m1 - m < 4) ? (m1 - m) : 4;
        for (int i = j; i < nr * 128; i += 384) {
            const int r = i >> 7, c = i & 127;
            const int mm = m + r;
            const float* src;
            if (mode == 0) {
                const int t = mm >> 6, b = mm & 63;
                src = X + ((size_t)b * TT + t) * DD;
            } else {
                src = g_h0 + (size_t)mm * HH;
            }
            sx[r][c] = src[c];
        }
        __syncthreads();

        u64 a0 = f2u(bj, 0.f), a1 = f2u(bj, 0.f), a2 = f2u(bj, 0.f), a3 = f2u(bj, 0.f);
        u64 b0 = 0, b1 = 0, b2 = 0, b3 = 0;
        const ulonglong2* r0 = (const ulonglong2*)sx[0];
        const ulonglong2* r1 = (const ulonglong2*)sx[1];
        const ulonglong2* r2 = (const ulonglong2*)sx[2];
        const ulonglong2* r3 = (const ulonglong2*)sx[3];
        #pragma unroll
        for (int k = 0; k < 32; k++) {
            ulonglong2 v0 = r0[k], v1 = r1[k], v2 = r2[k], v3 = r3[k];
            fma2(a0, v0.x, w[2*k]); fma2(b0, v0.y, w[2*k+1]);
            fma2(a1, v1.x, w[2*k]); fma2(b1, v1.y, w[2*k+1]);
            fma2(a2, v2.x, w[2*k]); fma2(b2, v2.y, w[2*k+1]);
            fma2(a3, v3.x, w[2*k]); fma2(b3, v3.y, w[2*k+1]);
        }
        if (nr > 0) g_gi[(size_t)(m + 0) * GG + j] = hsum(a0, b0);
        if (nr > 1) g_gi[(size_t)(m + 1) * GG + j] = hsum(a1, b1);
        if (nr > 2) g_gi[(size_t)(m + 2) * GG + j] = hsum(a2, b2);
        if (nr > 3) g_gi[(size_t)(m + 3) * GG + j] = hsum(a3, b3);
        __syncthreads();
    }
}

// ---------------------------------------------------------------------------
// Sequential GRU recurrence, one CTA per batch element. Thread j owns gate
// row j of W_hh as 64 packed f32x2 pairs; h broadcast from shared (LDS.128
// yields two packed operands directly).
// ---------------------------------------------------------------------------
__global__ __launch_bounds__(384, 1) void gru_rec(
    const float* __restrict__ Whh,
    const float* __restrict__ bhh,
    int store_h0,
    float* __restrict__ hout)
{
    const int j = threadIdx.x;
    const int b = blockIdx.x;

    u64 w[64];
    {
        const ulonglong2* wr = (const ulonglong2*)(Whh + (size_t)j * 128);
        #pragma unroll
        for (int k = 0; k < 32; k++) { ulonglong2 v = wr[k]; w[2*k] = v.x; w[2*k+1] = v.y; }
    }
    const float bj = bhh[j];

    __shared__ __align__(16) float s_h[128];
    __shared__ float s_gh[384];
    __shared__ float s_gin[128];

    if (j < 128) s_h[j] = 0.0f;
    __syncthreads();

    const float* gptr = g_gi + (size_t)b * GG + j;   // stride B*G per step
    float gval = gptr[0];

    for (int t = 0; t < TT; t++) {
        float gnext = (t + 1 < TT) ? gptr[(size_t)(t + 1) * BB * GG] : 0.0f;

        u64 acc0 = f2u(bj, 0.f), acc1 = 0;
        const ulonglong2* h16 = (const ulonglong2*)s_h;
        #pragma unroll
        for (int k = 0; k < 32; k++) {
            ulonglong2 hv = h16[k];          // broadcast LDS.128
            fma2(acc0, hv.x, w[2*k]);
            fma2(acc1, hv.y, w[2*k+1]);
        }
        const float acc = hsum(acc0, acc1);

        if (j < 256) {
            s_gh[j] = acc + gval;            // r,z rows: gi + gh fused
        } else {
            s_gh[j] = acc;                   // n row: gh kept separate
            s_gin[j - 256] = gval;
        }
        __syncthreads();

        if (j < 128) {
            const float r  = fsig(s_gh[j]   + 0.0f);
            const float z  = fsig(s_gh[j + 128]);
            const float n  = ftanh(s_gin[j] + r * s_gh[j + 256]);
            const float hn = (1.0f - z) * n + z * s_h[j];
            s_h[j] = hn;
            if (store_h0)
                g_h0[(size_t)t * BB * HH + (size_t)b * HH + j] = hn;
        }
        __syncthreads();
        gval = gnext;
    }

    if (j < 128) hout[(size_t)b * HH + j] = s_h[j];
}

extern "C" void kernel_launch(void* const* d_in, const int* in_sizes, int n_in,
                              void* d_out, int out_size)
{
    const float* x     = (const float*)d_in[0];
    const float* W_ih0 = (const float*)d_in[1];
    const float* W_hh0 = (const float*)d_in[2];
    const float* b_ih0 = (const float*)d_in[3];
    const float* b_hh0 = (const float*)d_in[4];
    const float* W_ih1 = (const float*)d_in[5];
    const float* W_hh1 = (const float*)d_in[6];
    const float* b_ih1 = (const float*)d_in[7];
    const float* b_hh1 = (const float*)d_in[8];
    float* out = (float*)d_out;   // [L=2, B, H]

    gi_gemm<<<148, 384>>>(x, W_ih0, b_ih0, /*mode=*/0);
    gru_rec<<<BB, 384>>>(W_hh0, b_hh0, /*store_h0=*/1, out);
    gi_gemm<<<148, 384>>>(nullptr, W_ih1, b_ih1, /*mode=*/1);
    gru_rec<<<BB, 384>>>(W_hh1, b_hh1, /*store_h0=*/0, out + BB * HH);
}